// round 11
// baseline (speedup 1.0000x reference)
#include <cuda_runtime.h>
#include <cuda_fp16.h>
#include <cstdint>

#define BB 2
#define DD 64
#define MAXN 50000
#define MAXE 800000
#define SCAN_B 1024

// ---------------- static device scratch (no allocations allowed) -----------
// NOTE: g_deg is self-cleaning — k_gather_final zeroes it after use, so every
// call to kernel_launch observes zeros (initial state is zero-initialized).
__device__ uint2 g_Ph[(size_t)MAXN * 32];      // fp16 P, [node][batch][64]
__device__ int   g_deg[MAXN];
__device__ int   g_off[MAXN + 1];              // block-local exclusive prefix
__device__ int   g_bsum[64];                   // per-scan-block base
__device__ uint2 g_rank[MAXE];                 // (rank_u, rank_v) per edge
__device__ uint2 g_adj[2 * MAXE];              // (nbr, gate-bits)

// ---------------- small helpers ---------------------------------------------
__device__ __forceinline__ unsigned long long pack2(float lo, float hi) {
    unsigned long long r;
    asm("mov.b64 %0, {%1, %2};" : "=l"(r) : "f"(lo), "f"(hi));
    return r;
}
__device__ __forceinline__ float2 unpack2(unsigned long long v) {
    float2 r;
    asm("mov.b64 {%0, %1}, %2;" : "=f"(r.x), "=f"(r.y) : "l"(v));
    return r;
}
__device__ __forceinline__ void ffma2(unsigned long long& d,
                                      unsigned long long a,
                                      unsigned long long b) {
    asm("fma.rn.f32x2 %0, %1, %2, %0;" : "+l"(d) : "l"(a), "l"(b));
}
__device__ __forceinline__ unsigned pack_h2(float a, float b) {
    __half2 h = __floats2half2_rn(a, b);
    return *reinterpret_cast<unsigned*>(&h);
}
__device__ __forceinline__ float2 unpack_h2(unsigned u) {
    __half2 h = *reinterpret_cast<__half2*>(&u);
    return __half22float2(h);
}

// ---------------------------------------------------------------------------
// Transform: P = prev @ W^T (fp32 math), store fp16 interleaved.
// ---------------------------------------------------------------------------
__global__ __launch_bounds__(256)
void k_transform(const float* __restrict__ prev, const float* __restrict__ W,
                 int nRows, int N)
{
    __shared__ float As[64][66];
    __shared__ float Wt[64][64];

    int tid = threadIdx.x;
    int row0 = blockIdx.x * 64;

#pragma unroll
    for (int j = 0; j < 4; j++) {
        int f4 = tid + j * 256;
        int e = f4 >> 4, k4 = f4 & 15;
        float4 w = reinterpret_cast<const float4*>(W)[f4];
        Wt[k4 * 4 + 0][e] = w.x;
        Wt[k4 * 4 + 1][e] = w.y;
        Wt[k4 * 4 + 2][e] = w.z;
        Wt[k4 * 4 + 3][e] = w.w;
    }
#pragma unroll
    for (int j = 0; j < 4; j++) {
        int f4 = tid + j * 256;
        int r = f4 >> 4, c4 = f4 & 15;
        float4 a = make_float4(0.f, 0.f, 0.f, 0.f);
        if (row0 + r < nRows)
            a = reinterpret_cast<const float4*>(prev)[(size_t)(row0 + r) * 16 + c4];
        As[c4 * 4 + 0][r] = a.x;
        As[c4 * 4 + 1][r] = a.y;
        As[c4 * 4 + 2][r] = a.z;
        As[c4 * 4 + 3][r] = a.w;
    }
    __syncthreads();

    int colg = tid & 15;
    int rowg = tid >> 4;

    unsigned long long acc[2][4] = {};

#pragma unroll 8
    for (int k = 0; k < 64; k++) {
        const unsigned long long* ar =
            reinterpret_cast<const unsigned long long*>(&As[k][rowg * 4]);
        unsigned long long A0 = ar[0];
        unsigned long long A1 = ar[1];
        float4 w = *reinterpret_cast<const float4*>(&Wt[k][colg * 4]);
        unsigned long long w0 = pack2(w.x, w.x);
        unsigned long long w1 = pack2(w.y, w.y);
        unsigned long long w2 = pack2(w.z, w.z);
        unsigned long long w3 = pack2(w.w, w.w);
        ffma2(acc[0][0], A0, w0); ffma2(acc[0][1], A0, w1);
        ffma2(acc[0][2], A0, w2); ffma2(acc[0][3], A0, w3);
        ffma2(acc[1][0], A1, w0); ffma2(acc[1][1], A1, w1);
        ffma2(acc[1][2], A1, w2); ffma2(acc[1][3], A1, w3);
    }

#pragma unroll
    for (int p = 0; p < 2; p++) {
        float2 v0 = unpack2(acc[p][0]);
        float2 v1 = unpack2(acc[p][1]);
        float2 v2 = unpack2(acc[p][2]);
        float2 v3 = unpack2(acc[p][3]);
        int rA = row0 + rowg * 4 + p * 2;
        int rB = rA + 1;
        if (rA < nRows) {
            int b = (rA >= N) ? 1 : 0;
            int n = rA - b * N;
            g_Ph[(size_t)n * 32 + b * 16 + colg] =
                make_uint2(pack_h2(v0.x, v1.x), pack_h2(v2.x, v3.x));
        }
        if (rB < nRows) {
            int b = (rB >= N) ? 1 : 0;
            int n = rB - b * N;
            g_Ph[(size_t)n * 32 + b * 16 + colg] =
                make_uint2(pack_h2(v0.y, v1.y), pack_h2(v2.y, v3.y));
        }
    }
}

// ---------------------------------------------------------------------------
// Count + rank, 2 edges per thread (single atomic pass).
// ---------------------------------------------------------------------------
__global__ __launch_bounds__(256)
void k_count_rank(const int* __restrict__ edges, int E)
{
    int i = blockIdx.x * blockDim.x + threadIdx.x;
    int Eh = E >> 1;
    if (i < Eh) {
        int4 e2 = reinterpret_cast<const int4*>(edges)[i];
        unsigned r0 = atomicAdd(&g_deg[e2.x], 1);
        unsigned r1 = atomicAdd(&g_deg[e2.y], 1);
        unsigned r2 = atomicAdd(&g_deg[e2.z], 1);
        unsigned r3 = atomicAdd(&g_deg[e2.w], 1);
        reinterpret_cast<uint4*>(g_rank)[i] = make_uint4(r0, r1, r2, r3);
    } else if (i == Eh && (E & 1)) {
        int e = E - 1;
        int u = edges[2 * (size_t)e];
        int v = edges[2 * (size_t)e + 1];
        unsigned ru = atomicAdd(&g_deg[u], 1);
        unsigned rv = atomicAdd(&g_deg[v], 1);
        g_rank[e] = make_uint2(ru, rv);
    }
}

// ---------------------------------------------------------------------------
// 2-phase scan: local prefix + block-sum scan. Bases folded into consumers.
// ---------------------------------------------------------------------------
__global__ __launch_bounds__(SCAN_B)
void k_scan_local(int N)
{
    __shared__ int sh[SCAN_B];
    int t = threadIdx.x;
    int i = blockIdx.x * SCAN_B + t;
    int d = (i < N) ? g_deg[i] : 0;
    sh[t] = d;
    __syncthreads();
    for (int s = 1; s < SCAN_B; s <<= 1) {
        int o = (t >= s) ? sh[t - s] : 0;
        __syncthreads();
        sh[t] += o;
        __syncthreads();
    }
    if (i < N) g_off[i] = sh[t] - d;          // block-local exclusive
    if (t == SCAN_B - 1) g_bsum[blockIdx.x] = sh[t];
}

__global__ __launch_bounds__(64)
void k_scan_bsum(int nBlocks)
{
    int t = threadIdx.x;
    int v = (t < nBlocks) ? g_bsum[t] : 0;
    __shared__ int sh[64];
    sh[t] = v;
    __syncthreads();
    for (int s = 1; s < 64; s <<= 1) {
        int o = (t >= s) ? sh[t - s] : 0;
        __syncthreads();
        sh[t] += o;
        __syncthreads();
    }
    if (t < nBlocks) g_bsum[t] = sh[t] - v;   // exclusive base per scan block
}

// ---------------------------------------------------------------------------
// Atomic-free fill, 2 edges per thread; absolute slot = local + bsum + rank.
// ---------------------------------------------------------------------------
__global__ __launch_bounds__(256)
void k_fill(const int* __restrict__ edges, const float* __restrict__ status,
            int E)
{
    int i = blockIdx.x * blockDim.x + threadIdx.x;
    int Eh = E >> 1;
    if (i < Eh) {
        int4  e2 = reinterpret_cast<const int4*>(edges)[i];
        uint4 r2 = reinterpret_cast<const uint4*>(g_rank)[i];
        float2 st = reinterpret_cast<const float2*>(status)[i];
        unsigned g0 = __float_as_uint(st.x);
        unsigned g1 = __float_as_uint(st.y);
        int o0 = g_off[e2.x] + g_bsum[e2.x >> 10] + (int)r2.x;
        int o1 = g_off[e2.y] + g_bsum[e2.y >> 10] + (int)r2.y;
        int o2 = g_off[e2.z] + g_bsum[e2.z >> 10] + (int)r2.z;
        int o3 = g_off[e2.w] + g_bsum[e2.w >> 10] + (int)r2.w;
        g_adj[o0] = make_uint2((unsigned)e2.y, g0);
        g_adj[o1] = make_uint2((unsigned)e2.x, g0);
        g_adj[o2] = make_uint2((unsigned)e2.w, g1);
        g_adj[o3] = make_uint2((unsigned)e2.z, g1);
    } else if (i == Eh && (E & 1)) {
        int e = E - 1;
        int u = edges[2 * (size_t)e];
        int v = edges[2 * (size_t)e + 1];
        uint2 r = g_rank[e];
        unsigned gb = __float_as_uint(status[e]);
        g_adj[g_off[u] + g_bsum[u >> 10] + (int)r.x] = make_uint2((unsigned)v, gb);
        g_adj[g_off[v] + g_bsum[v >> 10] + (int)r.y] = make_uint2((unsigned)u, gb);
    }
}

// ---------------------------------------------------------------------------
// Gather + epilogue: one warp per node, 8 loads in flight (default-cached
// loads — .cs proved harmful in R10). Self-cleans g_deg for the next call.
// ---------------------------------------------------------------------------
__global__ __launch_bounds__(128)
void k_gather_final(const float* __restrict__ nodef,
                    const float* __restrict__ edgef,
                    float* __restrict__ out, int N)
{
    int node = (blockIdx.x * blockDim.x + threadIdx.x) >> 5;
    if (node >= N) return;
    int lane = threadIdx.x & 31;

    int beg = __ldg(&g_off[node]) + __ldg(&g_bsum[node >> 10]);
    int end = beg + __ldg(&g_deg[node]);
    if (lane == 0) g_deg[node] = 0;           // self-clean for next call

    float4 acc0 = make_float4(0.f, 0.f, 0.f, 0.f);
    float4 acc1 = make_float4(0.f, 0.f, 0.f, 0.f);
    float4 acc2 = make_float4(0.f, 0.f, 0.f, 0.f);
    float4 acc3 = make_float4(0.f, 0.f, 0.f, 0.f);

    int e = beg;
    for (; e + 7 < end; e += 8) {
        uint2 a0 = g_adj[e];
        uint2 a1 = g_adj[e + 1];
        uint2 a2 = g_adj[e + 2];
        uint2 a3 = g_adj[e + 3];
        uint2 a4 = g_adj[e + 4];
        uint2 a5 = g_adj[e + 5];
        uint2 a6 = g_adj[e + 6];
        uint2 a7 = g_adj[e + 7];
        uint2 q0 = __ldg(g_Ph + (size_t)a0.x * 32 + lane);
        uint2 q1 = __ldg(g_Ph + (size_t)a1.x * 32 + lane);
        uint2 q2 = __ldg(g_Ph + (size_t)a2.x * 32 + lane);
        uint2 q3 = __ldg(g_Ph + (size_t)a3.x * 32 + lane);
        uint2 q4 = __ldg(g_Ph + (size_t)a4.x * 32 + lane);
        uint2 q5 = __ldg(g_Ph + (size_t)a5.x * 32 + lane);
        uint2 q6 = __ldg(g_Ph + (size_t)a6.x * 32 + lane);
        uint2 q7 = __ldg(g_Ph + (size_t)a7.x * 32 + lane);
        float g0 = __uint_as_float(a0.y);
        float g1 = __uint_as_float(a1.y);
        float g2 = __uint_as_float(a2.y);
        float g3 = __uint_as_float(a3.y);
        float g4 = __uint_as_float(a4.y);
        float g5 = __uint_as_float(a5.y);
        float g6 = __uint_as_float(a6.y);
        float g7 = __uint_as_float(a7.y);
        {
            float2 f01 = unpack_h2(q0.x), f23 = unpack_h2(q0.y);
            acc0.x += f01.x * g0; acc0.y += f01.y * g0;
            acc0.z += f23.x * g0; acc0.w += f23.y * g0;
        }
        {
            float2 f01 = unpack_h2(q1.x), f23 = unpack_h2(q1.y);
            acc1.x += f01.x * g1; acc1.y += f01.y * g1;
            acc1.z += f23.x * g1; acc1.w += f23.y * g1;
        }
        {
            float2 f01 = unpack_h2(q2.x), f23 = unpack_h2(q2.y);
            acc2.x += f01.x * g2; acc2.y += f01.y * g2;
            acc2.z += f23.x * g2; acc2.w += f23.y * g2;
        }
        {
            float2 f01 = unpack_h2(q3.x), f23 = unpack_h2(q3.y);
            acc3.x += f01.x * g3; acc3.y += f01.y * g3;
            acc3.z += f23.x * g3; acc3.w += f23.y * g3;
        }
        {
            float2 f01 = unpack_h2(q4.x), f23 = unpack_h2(q4.y);
            acc0.x += f01.x * g4; acc0.y += f01.y * g4;
            acc0.z += f23.x * g4; acc0.w += f23.y * g4;
        }
        {
            float2 f01 = unpack_h2(q5.x), f23 = unpack_h2(q5.y);
            acc1.x += f01.x * g5; acc1.y += f01.y * g5;
            acc1.z += f23.x * g5; acc1.w += f23.y * g5;
        }
        {
            float2 f01 = unpack_h2(q6.x), f23 = unpack_h2(q6.y);
            acc2.x += f01.x * g6; acc2.y += f01.y * g6;
            acc2.z += f23.x * g6; acc2.w += f23.y * g6;
        }
        {
            float2 f01 = unpack_h2(q7.x), f23 = unpack_h2(q7.y);
            acc3.x += f01.x * g7; acc3.y += f01.y * g7;
            acc3.z += f23.x * g7; acc3.w += f23.y * g7;
        }
    }
    for (; e < end; e++) {
        uint2 a0 = g_adj[e];
        float g0 = __uint_as_float(a0.y);
        uint2 q0 = __ldg(g_Ph + (size_t)a0.x * 32 + lane);
        float2 f01 = unpack_h2(q0.x), f23 = unpack_h2(q0.y);
        acc0.x += f01.x * g0; acc0.y += f01.y * g0;
        acc0.z += f23.x * g0; acc0.w += f23.y * g0;
    }

    int b = lane >> 4;
    int c = lane & 15;
    size_t o = ((size_t)b * N + node) * 16 + c;
    float4 nf = reinterpret_cast<const float4*>(nodef)[o];
    float4 ef = reinterpret_cast<const float4*>(edgef)[o];

    float4 s;
    s.x = nf.x + ef.x + (acc0.x + acc1.x) + (acc2.x + acc3.x);
    s.y = nf.y + ef.y + (acc0.y + acc1.y) + (acc2.y + acc3.y);
    s.z = nf.z + ef.z + (acc0.z + acc1.z) + (acc2.z + acc3.z);
    s.w = nf.w + ef.w + (acc0.w + acc1.w) + (acc2.w + acc3.w);
    s.x = (s.x >= 0.f) ? s.x : 0.01f * s.x;
    s.y = (s.y >= 0.f) ? s.y : 0.01f * s.y;
    s.z = (s.z >= 0.f) ? s.z : 0.01f * s.z;
    s.w = (s.w >= 0.f) ? s.w : 0.01f * s.w;

    reinterpret_cast<float4*>(out)[o] = s;
}

// ---------------------------------------------------------------------------
extern "C" void kernel_launch(void* const* d_in, const int* in_sizes, int n_in,
                              void* d_out, int out_size)
{
    const float* prev  = (const float*)d_in[0];
    const int*   edges = (const int*)  d_in[1];
    const float* nodef = (const float*)d_in[2];
    const float* edgef = (const float*)d_in[3];
    const float* stat  = (const float*)d_in[4];
    const float* W     = (const float*)d_in[5];
    float* out = (float*)d_out;

    int E     = in_sizes[4];
    int nRows = in_sizes[0] / DD;   // B*N
    int N     = nRows / BB;

    int Epair  = (E >> 1) + 1;
    int nScanB = (N + SCAN_B - 1) / SCAN_B;

    // g_deg arrives zeroed (module init on first call; self-cleaned after).
    k_count_rank<<<(Epair + 255) / 256, 256>>>(edges, E);
    k_scan_local<<<nScanB, SCAN_B>>>(N);
    k_scan_bsum <<<1, 64>>>(nScanB);
    k_fill      <<<(Epair + 255) / 256, 256>>>(edges, stat, E);

    k_transform<<<(nRows + 63) / 64, 256>>>(prev, W, nRows, N);

    long long th = (long long)N * 32;
    k_gather_final<<<(unsigned)((th + 127) / 128), 128>>>(nodef, edgef, out, N);
}

// round 12
// speedup vs baseline: 1.4823x; 1.4823x over previous
#include <cuda_runtime.h>
#include <cuda_fp16.h>
#include <cstdint>

#define BB 2
#define DD 64
#define MAXN 50000
#define MAXE 800000
#define SCAN_B 1024

// ---------------- static device scratch (no allocations allowed) -----------
__device__ uint2 g_Ph[(size_t)MAXN * 32];      // fp16 P, [node][batch][64]
__device__ int   g_deg[MAXN];
__device__ int   g_off[MAXN + 1];              // block-local exclusive prefix
__device__ int   g_bsum[64];                   // per-scan-block base
__device__ uint2 g_rank[MAXE];                 // (rank_u, rank_v) per edge
__device__ uint2 g_adj[2 * MAXE];              // (nbr, gate-bits)

// ---------------- small helpers ---------------------------------------------
__device__ __forceinline__ unsigned long long pack2(float lo, float hi) {
    unsigned long long r;
    asm("mov.b64 %0, {%1, %2};" : "=l"(r) : "f"(lo), "f"(hi));
    return r;
}
__device__ __forceinline__ float2 unpack2(unsigned long long v) {
    float2 r;
    asm("mov.b64 {%0, %1}, %2;" : "=f"(r.x), "=f"(r.y) : "l"(v));
    return r;
}
__device__ __forceinline__ void ffma2(unsigned long long& d,
                                      unsigned long long a,
                                      unsigned long long b) {
    asm("fma.rn.f32x2 %0, %1, %2, %0;" : "+l"(d) : "l"(a), "l"(b));
}
__device__ __forceinline__ unsigned pack_h2(float a, float b) {
    __half2 h = __floats2half2_rn(a, b);
    return *reinterpret_cast<unsigned*>(&h);
}
__device__ __forceinline__ float2 unpack_h2(unsigned u) {
    __half2 h = *reinterpret_cast<__half2*>(&u);
    return __half22float2(h);
}

// ---------------------------------------------------------------------------
// Transform: P = prev @ W^T (fp32 math), store fp16 interleaved.
// ---------------------------------------------------------------------------
__global__ __launch_bounds__(256)
void k_transform(const float* __restrict__ prev, const float* __restrict__ W,
                 int nRows, int N)
{
    __shared__ float As[64][66];
    __shared__ float Wt[64][64];

    int tid = threadIdx.x;
    int row0 = blockIdx.x * 64;

#pragma unroll
    for (int j = 0; j < 4; j++) {
        int f4 = tid + j * 256;
        int e = f4 >> 4, k4 = f4 & 15;
        float4 w = reinterpret_cast<const float4*>(W)[f4];
        Wt[k4 * 4 + 0][e] = w.x;
        Wt[k4 * 4 + 1][e] = w.y;
        Wt[k4 * 4 + 2][e] = w.z;
        Wt[k4 * 4 + 3][e] = w.w;
    }
#pragma unroll
    for (int j = 0; j < 4; j++) {
        int f4 = tid + j * 256;
        int r = f4 >> 4, c4 = f4 & 15;
        float4 a = make_float4(0.f, 0.f, 0.f, 0.f);
        if (row0 + r < nRows)
            a = reinterpret_cast<const float4*>(prev)[(size_t)(row0 + r) * 16 + c4];
        As[c4 * 4 + 0][r] = a.x;
        As[c4 * 4 + 1][r] = a.y;
        As[c4 * 4 + 2][r] = a.z;
        As[c4 * 4 + 3][r] = a.w;
    }
    __syncthreads();

    int colg = tid & 15;
    int rowg = tid >> 4;

    unsigned long long acc[2][4] = {};

#pragma unroll 8
    for (int k = 0; k < 64; k++) {
        const unsigned long long* ar =
            reinterpret_cast<const unsigned long long*>(&As[k][rowg * 4]);
        unsigned long long A0 = ar[0];
        unsigned long long A1 = ar[1];
        float4 w = *reinterpret_cast<const float4*>(&Wt[k][colg * 4]);
        unsigned long long w0 = pack2(w.x, w.x);
        unsigned long long w1 = pack2(w.y, w.y);
        unsigned long long w2 = pack2(w.z, w.z);
        unsigned long long w3 = pack2(w.w, w.w);
        ffma2(acc[0][0], A0, w0); ffma2(acc[0][1], A0, w1);
        ffma2(acc[0][2], A0, w2); ffma2(acc[0][3], A0, w3);
        ffma2(acc[1][0], A1, w0); ffma2(acc[1][1], A1, w1);
        ffma2(acc[1][2], A1, w2); ffma2(acc[1][3], A1, w3);
    }

#pragma unroll
    for (int p = 0; p < 2; p++) {
        float2 v0 = unpack2(acc[p][0]);
        float2 v1 = unpack2(acc[p][1]);
        float2 v2 = unpack2(acc[p][2]);
        float2 v3 = unpack2(acc[p][3]);
        int rA = row0 + rowg * 4 + p * 2;
        int rB = rA + 1;
        if (rA < nRows) {
            int b = (rA >= N) ? 1 : 0;
            int n = rA - b * N;
            g_Ph[(size_t)n * 32 + b * 16 + colg] =
                make_uint2(pack_h2(v0.x, v1.x), pack_h2(v2.x, v3.x));
        }
        if (rB < nRows) {
            int b = (rB >= N) ? 1 : 0;
            int n = rB - b * N;
            g_Ph[(size_t)n * 32 + b * 16 + colg] =
                make_uint2(pack_h2(v0.y, v1.y), pack_h2(v2.y, v3.y));
        }
    }
}

// ---------------------------------------------------------------------------
// Count + rank, 2 edges per thread (single atomic pass).
// ---------------------------------------------------------------------------
__global__ __launch_bounds__(256)
void k_count_rank(const int* __restrict__ edges, int E)
{
    int i = blockIdx.x * blockDim.x + threadIdx.x;
    int Eh = E >> 1;
    if (i < Eh) {
        int4 e2 = reinterpret_cast<const int4*>(edges)[i];
        unsigned r0 = atomicAdd(&g_deg[e2.x], 1);
        unsigned r1 = atomicAdd(&g_deg[e2.y], 1);
        unsigned r2 = atomicAdd(&g_deg[e2.z], 1);
        unsigned r3 = atomicAdd(&g_deg[e2.w], 1);
        reinterpret_cast<uint4*>(g_rank)[i] = make_uint4(r0, r1, r2, r3);
    } else if (i == Eh && (E & 1)) {
        int e = E - 1;
        int u = edges[2 * (size_t)e];
        int v = edges[2 * (size_t)e + 1];
        unsigned ru = atomicAdd(&g_deg[u], 1);
        unsigned rv = atomicAdd(&g_deg[v], 1);
        g_rank[e] = make_uint2(ru, rv);
    }
}

// ---------------------------------------------------------------------------
// 2-phase scan: local prefix + block-sum scan. Bases folded into consumers.
// ---------------------------------------------------------------------------
__global__ __launch_bounds__(SCAN_B)
void k_scan_local(int N)
{
    __shared__ int sh[SCAN_B];
    int t = threadIdx.x;
    int i = blockIdx.x * SCAN_B + t;
    int d = (i < N) ? g_deg[i] : 0;
    sh[t] = d;
    __syncthreads();
    for (int s = 1; s < SCAN_B; s <<= 1) {
        int o = (t >= s) ? sh[t - s] : 0;
        __syncthreads();
        sh[t] += o;
        __syncthreads();
    }
    if (i < N) g_off[i] = sh[t] - d;          // block-local exclusive
    if (t == SCAN_B - 1) g_bsum[blockIdx.x] = sh[t];
}

__global__ __launch_bounds__(64)
void k_scan_bsum(int nBlocks)
{
    int t = threadIdx.x;
    int v = (t < nBlocks) ? g_bsum[t] : 0;
    __shared__ int sh[64];
    sh[t] = v;
    __syncthreads();
    for (int s = 1; s < 64; s <<= 1) {
        int o = (t >= s) ? sh[t - s] : 0;
        __syncthreads();
        sh[t] += o;
        __syncthreads();
    }
    if (t < nBlocks) g_bsum[t] = sh[t] - v;   // exclusive base per scan block
}

// ---------------------------------------------------------------------------
// Atomic-free fill, 2 edges per thread; absolute slot = local + bsum + rank.
// ---------------------------------------------------------------------------
__global__ __launch_bounds__(256)
void k_fill(const int* __restrict__ edges, const float* __restrict__ status,
            int E)
{
    int i = blockIdx.x * blockDim.x + threadIdx.x;
    int Eh = E >> 1;
    if (i < Eh) {
        int4  e2 = reinterpret_cast<const int4*>(edges)[i];
        uint4 r2 = reinterpret_cast<const uint4*>(g_rank)[i];
        float2 st = reinterpret_cast<const float2*>(status)[i];
        unsigned g0 = __float_as_uint(st.x);
        unsigned g1 = __float_as_uint(st.y);
        int o0 = g_off[e2.x] + g_bsum[e2.x >> 10] + (int)r2.x;
        int o1 = g_off[e2.y] + g_bsum[e2.y >> 10] + (int)r2.y;
        int o2 = g_off[e2.z] + g_bsum[e2.z >> 10] + (int)r2.z;
        int o3 = g_off[e2.w] + g_bsum[e2.w >> 10] + (int)r2.w;
        g_adj[o0] = make_uint2((unsigned)e2.y, g0);
        g_adj[o1] = make_uint2((unsigned)e2.x, g0);
        g_adj[o2] = make_uint2((unsigned)e2.w, g1);
        g_adj[o3] = make_uint2((unsigned)e2.z, g1);
    } else if (i == Eh && (E & 1)) {
        int e = E - 1;
        int u = edges[2 * (size_t)e];
        int v = edges[2 * (size_t)e + 1];
        uint2 r = g_rank[e];
        unsigned gb = __float_as_uint(status[e]);
        g_adj[g_off[u] + g_bsum[u >> 10] + (int)r.x] = make_uint2((unsigned)v, gb);
        g_adj[g_off[v] + g_bsum[v >> 10] + (int)r.y] = make_uint2((unsigned)u, gb);
    }
}

// ---------------------------------------------------------------------------
// Gather + epilogue: one warp per node, 8 loads in flight.
// 128-thread blocks for higher reg-limited occupancy.
// ---------------------------------------------------------------------------
__global__ __launch_bounds__(128)
void k_gather_final(const float* __restrict__ nodef,
                    const float* __restrict__ edgef,
                    float* __restrict__ out, int N)
{
    int node = (blockIdx.x * blockDim.x + threadIdx.x) >> 5;
    if (node >= N) return;
    int lane = threadIdx.x & 31;

    int beg = __ldg(&g_off[node]) + __ldg(&g_bsum[node >> 10]);
    int end = beg + __ldg(&g_deg[node]);

    float4 acc0 = make_float4(0.f, 0.f, 0.f, 0.f);
    float4 acc1 = make_float4(0.f, 0.f, 0.f, 0.f);
    float4 acc2 = make_float4(0.f, 0.f, 0.f, 0.f);
    float4 acc3 = make_float4(0.f, 0.f, 0.f, 0.f);

    int e = beg;
    for (; e + 7 < end; e += 8) {
        uint2 a0 = g_adj[e];
        uint2 a1 = g_adj[e + 1];
        uint2 a2 = g_adj[e + 2];
        uint2 a3 = g_adj[e + 3];
        uint2 a4 = g_adj[e + 4];
        uint2 a5 = g_adj[e + 5];
        uint2 a6 = g_adj[e + 6];
        uint2 a7 = g_adj[e + 7];
        uint2 q0 = __ldg(g_Ph + (size_t)a0.x * 32 + lane);
        uint2 q1 = __ldg(g_Ph + (size_t)a1.x * 32 + lane);
        uint2 q2 = __ldg(g_Ph + (size_t)a2.x * 32 + lane);
        uint2 q3 = __ldg(g_Ph + (size_t)a3.x * 32 + lane);
        uint2 q4 = __ldg(g_Ph + (size_t)a4.x * 32 + lane);
        uint2 q5 = __ldg(g_Ph + (size_t)a5.x * 32 + lane);
        uint2 q6 = __ldg(g_Ph + (size_t)a6.x * 32 + lane);
        uint2 q7 = __ldg(g_Ph + (size_t)a7.x * 32 + lane);
        float g0 = __uint_as_float(a0.y);
        float g1 = __uint_as_float(a1.y);
        float g2 = __uint_as_float(a2.y);
        float g3 = __uint_as_float(a3.y);
        float g4 = __uint_as_float(a4.y);
        float g5 = __uint_as_float(a5.y);
        float g6 = __uint_as_float(a6.y);
        float g7 = __uint_as_float(a7.y);
        {
            float2 f01 = unpack_h2(q0.x), f23 = unpack_h2(q0.y);
            acc0.x += f01.x * g0; acc0.y += f01.y * g0;
            acc0.z += f23.x * g0; acc0.w += f23.y * g0;
        }
        {
            float2 f01 = unpack_h2(q1.x), f23 = unpack_h2(q1.y);
            acc1.x += f01.x * g1; acc1.y += f01.y * g1;
            acc1.z += f23.x * g1; acc1.w += f23.y * g1;
        }
        {
            float2 f01 = unpack_h2(q2.x), f23 = unpack_h2(q2.y);
            acc2.x += f01.x * g2; acc2.y += f01.y * g2;
            acc2.z += f23.x * g2; acc2.w += f23.y * g2;
        }
        {
            float2 f01 = unpack_h2(q3.x), f23 = unpack_h2(q3.y);
            acc3.x += f01.x * g3; acc3.y += f01.y * g3;
            acc3.z += f23.x * g3; acc3.w += f23.y * g3;
        }
        {
            float2 f01 = unpack_h2(q4.x), f23 = unpack_h2(q4.y);
            acc0.x += f01.x * g4; acc0.y += f01.y * g4;
            acc0.z += f23.x * g4; acc0.w += f23.y * g4;
        }
        {
            float2 f01 = unpack_h2(q5.x), f23 = unpack_h2(q5.y);
            acc1.x += f01.x * g5; acc1.y += f01.y * g5;
            acc1.z += f23.x * g5; acc1.w += f23.y * g5;
        }
        {
            float2 f01 = unpack_h2(q6.x), f23 = unpack_h2(q6.y);
            acc2.x += f01.x * g6; acc2.y += f01.y * g6;
            acc2.z += f23.x * g6; acc2.w += f23.y * g6;
        }
        {
            float2 f01 = unpack_h2(q7.x), f23 = unpack_h2(q7.y);
            acc3.x += f01.x * g7; acc3.y += f01.y * g7;
            acc3.z += f23.x * g7; acc3.w += f23.y * g7;
        }
    }
    for (; e < end; e++) {
        uint2 a0 = g_adj[e];
        float g0 = __uint_as_float(a0.y);
        uint2 q0 = __ldg(g_Ph + (size_t)a0.x * 32 + lane);
        float2 f01 = unpack_h2(q0.x), f23 = unpack_h2(q0.y);
        acc0.x += f01.x * g0; acc0.y += f01.y * g0;
        acc0.z += f23.x * g0; acc0.w += f23.y * g0;
    }

    int b = lane >> 4;
    int c = lane & 15;
    size_t o = ((size_t)b * N + node) * 16 + c;
    float4 nf = reinterpret_cast<const float4*>(nodef)[o];
    float4 ef = reinterpret_cast<const float4*>(edgef)[o];

    float4 s;
    s.x = nf.x + ef.x + (acc0.x + acc1.x) + (acc2.x + acc3.x);
    s.y = nf.y + ef.y + (acc0.y + acc1.y) + (acc2.y + acc3.y);
    s.z = nf.z + ef.z + (acc0.z + acc1.z) + (acc2.z + acc3.z);
    s.w = nf.w + ef.w + (acc0.w + acc1.w) + (acc2.w + acc3.w);
    s.x = (s.x >= 0.f) ? s.x : 0.01f * s.x;
    s.y = (s.y >= 0.f) ? s.y : 0.01f * s.y;
    s.z = (s.z >= 0.f) ? s.z : 0.01f * s.z;
    s.w = (s.w >= 0.f) ? s.w : 0.01f * s.w;

    reinterpret_cast<float4*>(out)[o] = s;
}

// ---------------------------------------------------------------------------
extern "C" void kernel_launch(void* const* d_in, const int* in_sizes, int n_in,
                              void* d_out, int out_size)
{
    const float* prev  = (const float*)d_in[0];
    const int*   edges = (const int*)  d_in[1];
    const float* nodef = (const float*)d_in[2];
    const float* edgef = (const float*)d_in[3];
    const float* stat  = (const float*)d_in[4];
    const float* W     = (const float*)d_in[5];
    float* out = (float*)d_out;

    int E     = in_sizes[4];
    int nRows = in_sizes[0] / DD;   // B*N
    int N     = nRows / BB;

    int Epair  = (E >> 1) + 1;
    int nScanB = (N + SCAN_B - 1) / SCAN_B;

    void* degPtr = nullptr;
    cudaGetSymbolAddress(&degPtr, g_deg);
    cudaMemsetAsync(degPtr, 0, (size_t)N * sizeof(int));

    k_count_rank<<<(Epair + 255) / 256, 256>>>(edges, E);
    k_scan_local<<<nScanB, SCAN_B>>>(N);
    k_scan_bsum <<<1, 64>>>(nScanB);
    k_fill      <<<(Epair + 255) / 256, 256>>>(edges, stat, E);

    k_transform<<<(nRows + 63) / 64, 256>>>(prev, W, nRows, N);

    long long th = (long long)N * 32;
    k_gather_final<<<(unsigned)((th + 127) / 128), 128>>>(nodef, edgef, out, N);
}

// round 13
// speedup vs baseline: 1.5096x; 1.0184x over previous
#include <cuda_runtime.h>
#include <cuda_fp16.h>
#include <cstdint>

#define BB 2
#define DD 64
#define MAXN 50000
#define MAXE 800000
#define SCAN_B 1024
#define TRANS_BLOCKS 296   // 2 blocks/SM x 148 SMs: single-wave persistent grid

// ---------------- static device scratch (no allocations allowed) -----------
__device__ uint2 g_Ph[(size_t)MAXN * 32];      // fp16 P, [node][batch][64]
__device__ int   g_deg[MAXN];
__device__ int   g_off[MAXN + 1];              // block-local exclusive prefix
__device__ int   g_bsum[64];                   // per-scan-block base
__device__ uint2 g_rank[MAXE];                 // (rank_u, rank_v) per edge
__device__ uint2 g_adj[2 * MAXE];              // (nbr, gate-bits)

// ---------------- PDL intrinsics (sm_90+) -----------------------------------
__device__ __forceinline__ void gdc_wait() {
    asm volatile("griddepcontrol.wait;" ::: "memory");
}
__device__ __forceinline__ void gdc_launch_dependents() {
    asm volatile("griddepcontrol.launch_dependents;");
}

// ---------------- small helpers ---------------------------------------------
__device__ __forceinline__ unsigned long long pack2(float lo, float hi) {
    unsigned long long r;
    asm("mov.b64 %0, {%1, %2};" : "=l"(r) : "f"(lo), "f"(hi));
    return r;
}
__device__ __forceinline__ float2 unpack2(unsigned long long v) {
    float2 r;
    asm("mov.b64 {%0, %1}, %2;" : "=f"(r.x), "=f"(r.y) : "l"(v));
    return r;
}
__device__ __forceinline__ void ffma2(unsigned long long& d,
                                      unsigned long long a,
                                      unsigned long long b) {
    asm("fma.rn.f32x2 %0, %1, %2, %0;" : "+l"(d) : "l"(a), "l"(b));
}
__device__ __forceinline__ unsigned pack_h2(float a, float b) {
    __half2 h = __floats2half2_rn(a, b);
    return *reinterpret_cast<unsigned*>(&h);
}
__device__ __forceinline__ float2 unpack_h2(unsigned u) {
    __half2 h = *reinterpret_cast<__half2*>(&u);
    return __half22float2(h);
}

// ---------------------------------------------------------------------------
// Transform: P = prev @ W^T (fp32 math), store fp16 interleaved.
// Persistent grid (TRANS_BLOCKS), grid-stride over 64-row tiles.
// Triggers PDL dependents at t~0 so the CSR build runs concurrently.
// ---------------------------------------------------------------------------
__global__ __launch_bounds__(256)
void k_transform(const float* __restrict__ prev, const float* __restrict__ W,
                 int nRows, int N)
{
    gdc_launch_dependents();   // all blocks resident in wave 1 -> fires at t~0

    __shared__ float As[64][66];
    __shared__ float Wt[64][64];

    int tid = threadIdx.x;

    // Load W once (tile-invariant).
#pragma unroll
    for (int j = 0; j < 4; j++) {
        int f4 = tid + j * 256;
        int e = f4 >> 4, k4 = f4 & 15;
        float4 w = reinterpret_cast<const float4*>(W)[f4];
        Wt[k4 * 4 + 0][e] = w.x;
        Wt[k4 * 4 + 1][e] = w.y;
        Wt[k4 * 4 + 2][e] = w.z;
        Wt[k4 * 4 + 3][e] = w.w;
    }

    int nTiles = (nRows + 63) >> 6;
    int colg = tid & 15;
    int rowg = tid >> 4;

    for (int tile = blockIdx.x; tile < nTiles; tile += gridDim.x) {
        int row0 = tile * 64;
        __syncthreads();   // protect As (and Wt on first iter)

#pragma unroll
        for (int j = 0; j < 4; j++) {
            int f4 = tid + j * 256;
            int r = f4 >> 4, c4 = f4 & 15;
            float4 a = make_float4(0.f, 0.f, 0.f, 0.f);
            if (row0 + r < nRows)
                a = reinterpret_cast<const float4*>(prev)[(size_t)(row0 + r) * 16 + c4];
            As[c4 * 4 + 0][r] = a.x;
            As[c4 * 4 + 1][r] = a.y;
            As[c4 * 4 + 2][r] = a.z;
            As[c4 * 4 + 3][r] = a.w;
        }
        __syncthreads();

        unsigned long long acc[2][4] = {};

#pragma unroll 8
        for (int k = 0; k < 64; k++) {
            const unsigned long long* ar =
                reinterpret_cast<const unsigned long long*>(&As[k][rowg * 4]);
            unsigned long long A0 = ar[0];
            unsigned long long A1 = ar[1];
            float4 w = *reinterpret_cast<const float4*>(&Wt[k][colg * 4]);
            unsigned long long w0 = pack2(w.x, w.x);
            unsigned long long w1 = pack2(w.y, w.y);
            unsigned long long w2 = pack2(w.z, w.z);
            unsigned long long w3 = pack2(w.w, w.w);
            ffma2(acc[0][0], A0, w0); ffma2(acc[0][1], A0, w1);
            ffma2(acc[0][2], A0, w2); ffma2(acc[0][3], A0, w3);
            ffma2(acc[1][0], A1, w0); ffma2(acc[1][1], A1, w1);
            ffma2(acc[1][2], A1, w2); ffma2(acc[1][3], A1, w3);
        }

#pragma unroll
        for (int p = 0; p < 2; p++) {
            float2 v0 = unpack2(acc[p][0]);
            float2 v1 = unpack2(acc[p][1]);
            float2 v2 = unpack2(acc[p][2]);
            float2 v3 = unpack2(acc[p][3]);
            int rA = row0 + rowg * 4 + p * 2;
            int rB = rA + 1;
            if (rA < nRows) {
                int b = (rA >= N) ? 1 : 0;
                int n = rA - b * N;
                g_Ph[(size_t)n * 32 + b * 16 + colg] =
                    make_uint2(pack_h2(v0.x, v1.x), pack_h2(v2.x, v3.x));
            }
            if (rB < nRows) {
                int b = (rB >= N) ? 1 : 0;
                int n = rB - b * N;
                g_Ph[(size_t)n * 32 + b * 16 + colg] =
                    make_uint2(pack_h2(v0.y, v1.y), pack_h2(v2.y, v3.y));
            }
        }
    }
}

// ---------------------------------------------------------------------------
// Count + rank, 2 edges per thread (single atomic pass).
// PDL secondary of k_transform; fully independent -> no wait.
// ---------------------------------------------------------------------------
__global__ __launch_bounds__(256)
void k_count_rank(const int* __restrict__ edges, int E)
{
    gdc_launch_dependents();
    int i = blockIdx.x * blockDim.x + threadIdx.x;
    int Eh = E >> 1;
    if (i < Eh) {
        int4 e2 = reinterpret_cast<const int4*>(edges)[i];
        unsigned r0 = atomicAdd(&g_deg[e2.x], 1);
        unsigned r1 = atomicAdd(&g_deg[e2.y], 1);
        unsigned r2 = atomicAdd(&g_deg[e2.z], 1);
        unsigned r3 = atomicAdd(&g_deg[e2.w], 1);
        reinterpret_cast<uint4*>(g_rank)[i] = make_uint4(r0, r1, r2, r3);
    } else if (i == Eh && (E & 1)) {
        int e = E - 1;
        int u = edges[2 * (size_t)e];
        int v = edges[2 * (size_t)e + 1];
        unsigned ru = atomicAdd(&g_deg[u], 1);
        unsigned rv = atomicAdd(&g_deg[v], 1);
        g_rank[e] = make_uint2(ru, rv);
    }
}

// ---------------------------------------------------------------------------
// 2-phase scan: local prefix + block-sum scan. Bases folded into consumers.
// Both PDL secondaries: pre-launch, wait for primary's memory.
// ---------------------------------------------------------------------------
__global__ __launch_bounds__(SCAN_B)
void k_scan_local(int N)
{
    gdc_launch_dependents();
    gdc_wait();                       // count's g_deg fully visible
    __shared__ int sh[SCAN_B];
    int t = threadIdx.x;
    int i = blockIdx.x * SCAN_B + t;
    int d = (i < N) ? g_deg[i] : 0;
    sh[t] = d;
    __syncthreads();
    for (int s = 1; s < SCAN_B; s <<= 1) {
        int o = (t >= s) ? sh[t - s] : 0;
        __syncthreads();
        sh[t] += o;
        __syncthreads();
    }
    if (i < N) g_off[i] = sh[t] - d;          // block-local exclusive
    if (t == SCAN_B - 1) g_bsum[blockIdx.x] = sh[t];
}

__global__ __launch_bounds__(64)
void k_scan_bsum(int nBlocks)
{
    gdc_launch_dependents();
    gdc_wait();
    int t = threadIdx.x;
    int v = (t < nBlocks) ? g_bsum[t] : 0;
    __shared__ int sh[64];
    sh[t] = v;
    __syncthreads();
    for (int s = 1; s < 64; s <<= 1) {
        int o = (t >= s) ? sh[t - s] : 0;
        __syncthreads();
        sh[t] += o;
        __syncthreads();
    }
    if (t < nBlocks) g_bsum[t] = sh[t] - v;   // exclusive base per scan block
}

// ---------------------------------------------------------------------------
// Atomic-free fill, 2 edges per thread; absolute slot = local + bsum + rank.
// PDL secondary of k_scan_bsum.
// ---------------------------------------------------------------------------
__global__ __launch_bounds__(256)
void k_fill(const int* __restrict__ edges, const float* __restrict__ status,
            int E)
{
    gdc_wait();                       // scan results fully visible
    int i = blockIdx.x * blockDim.x + threadIdx.x;
    int Eh = E >> 1;
    if (i < Eh) {
        int4  e2 = reinterpret_cast<const int4*>(edges)[i];
        uint4 r2 = reinterpret_cast<const uint4*>(g_rank)[i];
        float2 st = reinterpret_cast<const float2*>(status)[i];
        unsigned g0 = __float_as_uint(st.x);
        unsigned g1 = __float_as_uint(st.y);
        int o0 = g_off[e2.x] + g_bsum[e2.x >> 10] + (int)r2.x;
        int o1 = g_off[e2.y] + g_bsum[e2.y >> 10] + (int)r2.y;
        int o2 = g_off[e2.z] + g_bsum[e2.z >> 10] + (int)r2.z;
        int o3 = g_off[e2.w] + g_bsum[e2.w >> 10] + (int)r2.w;
        g_adj[o0] = make_uint2((unsigned)e2.y, g0);
        g_adj[o1] = make_uint2((unsigned)e2.x, g0);
        g_adj[o2] = make_uint2((unsigned)e2.w, g1);
        g_adj[o3] = make_uint2((unsigned)e2.z, g1);
    } else if (i == Eh && (E & 1)) {
        int e = E - 1;
        int u = edges[2 * (size_t)e];
        int v = edges[2 * (size_t)e + 1];
        uint2 r = g_rank[e];
        unsigned gb = __float_as_uint(status[e]);
        g_adj[g_off[u] + g_bsum[u >> 10] + (int)r.x] = make_uint2((unsigned)v, gb);
        g_adj[g_off[v] + g_bsum[v >> 10] + (int)r.y] = make_uint2((unsigned)u, gb);
    }
}

// ---------------------------------------------------------------------------
// Gather + epilogue: one warp per node, 8 loads in flight. NORMAL launch —
// must wait for BOTH fill and the concurrently-running transform.
// ---------------------------------------------------------------------------
__global__ __launch_bounds__(128)
void k_gather_final(const float* __restrict__ nodef,
                    const float* __restrict__ edgef,
                    float* __restrict__ out, int N)
{
    int node = (blockIdx.x * blockDim.x + threadIdx.x) >> 5;
    if (node >= N) return;
    int lane = threadIdx.x & 31;

    int beg = __ldg(&g_off[node]) + __ldg(&g_bsum[node >> 10]);
    int end = beg + __ldg(&g_deg[node]);

    float4 acc0 = make_float4(0.f, 0.f, 0.f, 0.f);
    float4 acc1 = make_float4(0.f, 0.f, 0.f, 0.f);
    float4 acc2 = make_float4(0.f, 0.f, 0.f, 0.f);
    float4 acc3 = make_float4(0.f, 0.f, 0.f, 0.f);

    int e = beg;
    for (; e + 7 < end; e += 8) {
        uint2 a0 = g_adj[e];
        uint2 a1 = g_adj[e + 1];
        uint2 a2 = g_adj[e + 2];
        uint2 a3 = g_adj[e + 3];
        uint2 a4 = g_adj[e + 4];
        uint2 a5 = g_adj[e + 5];
        uint2 a6 = g_adj[e + 6];
        uint2 a7 = g_adj[e + 7];
        uint2 q0 = __ldg(g_Ph + (size_t)a0.x * 32 + lane);
        uint2 q1 = __ldg(g_Ph + (size_t)a1.x * 32 + lane);
        uint2 q2 = __ldg(g_Ph + (size_t)a2.x * 32 + lane);
        uint2 q3 = __ldg(g_Ph + (size_t)a3.x * 32 + lane);
        uint2 q4 = __ldg(g_Ph + (size_t)a4.x * 32 + lane);
        uint2 q5 = __ldg(g_Ph + (size_t)a5.x * 32 + lane);
        uint2 q6 = __ldg(g_Ph + (size_t)a6.x * 32 + lane);
        uint2 q7 = __ldg(g_Ph + (size_t)a7.x * 32 + lane);
        float g0 = __uint_as_float(a0.y);
        float g1 = __uint_as_float(a1.y);
        float g2 = __uint_as_float(a2.y);
        float g3 = __uint_as_float(a3.y);
        float g4 = __uint_as_float(a4.y);
        float g5 = __uint_as_float(a5.y);
        float g6 = __uint_as_float(a6.y);
        float g7 = __uint_as_float(a7.y);
        {
            float2 f01 = unpack_h2(q0.x), f23 = unpack_h2(q0.y);
            acc0.x += f01.x * g0; acc0.y += f01.y * g0;
            acc0.z += f23.x * g0; acc0.w += f23.y * g0;
        }
        {
            float2 f01 = unpack_h2(q1.x), f23 = unpack_h2(q1.y);
            acc1.x += f01.x * g1; acc1.y += f01.y * g1;
            acc1.z += f23.x * g1; acc1.w += f23.y * g1;
        }
        {
            float2 f01 = unpack_h2(q2.x), f23 = unpack_h2(q2.y);
            acc2.x += f01.x * g2; acc2.y += f01.y * g2;
            acc2.z += f23.x * g2; acc2.w += f23.y * g2;
        }
        {
            float2 f01 = unpack_h2(q3.x), f23 = unpack_h2(q3.y);
            acc3.x += f01.x * g3; acc3.y += f01.y * g3;
            acc3.z += f23.x * g3; acc3.w += f23.y * g3;
        }
        {
            float2 f01 = unpack_h2(q4.x), f23 = unpack_h2(q4.y);
            acc0.x += f01.x * g4; acc0.y += f01.y * g4;
            acc0.z += f23.x * g4; acc0.w += f23.y * g4;
        }
        {
            float2 f01 = unpack_h2(q5.x), f23 = unpack_h2(q5.y);
            acc1.x += f01.x * g5; acc1.y += f01.y * g5;
            acc1.z += f23.x * g5; acc1.w += f23.y * g5;
        }
        {
            float2 f01 = unpack_h2(q6.x), f23 = unpack_h2(q6.y);
            acc2.x += f01.x * g6; acc2.y += f01.y * g6;
            acc2.z += f23.x * g6; acc2.w += f23.y * g6;
        }
        {
            float2 f01 = unpack_h2(q7.x), f23 = unpack_h2(q7.y);
            acc3.x += f01.x * g7; acc3.y += f01.y * g7;
            acc3.z += f23.x * g7; acc3.w += f23.y * g7;
        }
    }
    for (; e < end; e++) {
        uint2 a0 = g_adj[e];
        float g0 = __uint_as_float(a0.y);
        uint2 q0 = __ldg(g_Ph + (size_t)a0.x * 32 + lane);
        float2 f01 = unpack_h2(q0.x), f23 = unpack_h2(q0.y);
        acc0.x += f01.x * g0; acc0.y += f01.y * g0;
        acc0.z += f23.x * g0; acc0.w += f23.y * g0;
    }

    int b = lane >> 4;
    int c = lane & 15;
    size_t o = ((size_t)b * N + node) * 16 + c;
    float4 nf = reinterpret_cast<const float4*>(nodef)[o];
    float4 ef = reinterpret_cast<const float4*>(edgef)[o];

    float4 s;
    s.x = nf.x + ef.x + (acc0.x + acc1.x) + (acc2.x + acc3.x);
    s.y = nf.y + ef.y + (acc0.y + acc1.y) + (acc2.y + acc3.y);
    s.z = nf.z + ef.z + (acc0.z + acc1.z) + (acc2.z + acc3.z);
    s.w = nf.w + ef.w + (acc0.w + acc1.w) + (acc2.w + acc3.w);
    s.x = (s.x >= 0.f) ? s.x : 0.01f * s.x;
    s.y = (s.y >= 0.f) ? s.y : 0.01f * s.y;
    s.z = (s.z >= 0.f) ? s.z : 0.01f * s.z;
    s.w = (s.w >= 0.f) ? s.w : 0.01f * s.w;

    reinterpret_cast<float4*>(out)[o] = s;
}

// ---------------------------------------------------------------------------
// Host-side PDL launch helper.
// ---------------------------------------------------------------------------
template <typename K, typename... Args>
static inline void launch_pdl(K kernel, dim3 grid, dim3 block, Args... args)
{
    cudaLaunchConfig_t cfg = {};
    cfg.gridDim = grid;
    cfg.blockDim = block;
    cfg.dynamicSmemBytes = 0;
    cfg.stream = 0;
    cudaLaunchAttribute attr[1];
    attr[0].id = cudaLaunchAttributeProgrammaticStreamSerialization;
    attr[0].val.programmaticStreamSerializationAllowed = 1;
    cfg.attrs = attr;
    cfg.numAttrs = 1;
    cudaLaunchKernelEx(&cfg, kernel, args...);
}

extern "C" void kernel_launch(void* const* d_in, const int* in_sizes, int n_in,
                              void* d_out, int out_size)
{
    const float* prev  = (const float*)d_in[0];
    const int*   edges = (const int*)  d_in[1];
    const float* nodef = (const float*)d_in[2];
    const float* edgef = (const float*)d_in[3];
    const float* stat  = (const float*)d_in[4];
    const float* W     = (const float*)d_in[5];
    float* out = (float*)d_out;

    int E     = in_sizes[4];
    int nRows = in_sizes[0] / DD;   // B*N
    int N     = nRows / BB;

    int Epair  = (E >> 1) + 1;
    int nScanB = (N + SCAN_B - 1) / SCAN_B;

    void* degPtr = nullptr;
    cudaGetSymbolAddress(&degPtr, g_deg);
    cudaMemsetAsync(degPtr, 0, (size_t)N * sizeof(int));

    // Persistent transform triggers dependents at t~0; build chain overlaps it.
    k_transform<<<TRANS_BLOCKS, 256>>>(prev, W, nRows, N);

    launch_pdl(k_count_rank, dim3((Epair + 255) / 256), dim3(256), edges, E);
    launch_pdl(k_scan_local, dim3(nScanB), dim3(SCAN_B), N);
    launch_pdl(k_scan_bsum,  dim3(1), dim3(64), nScanB);
    launch_pdl(k_fill,       dim3((Epair + 255) / 256), dim3(256), edges, stat, E);

    // Normal launch: must wait for BOTH fill and transform.
    long long th = (long long)N * 32;
    k_gather_final<<<(unsigned)((th + 127) / 128), 128>>>(nodef, edgef, out, N);
}

// round 14
// speedup vs baseline: 1.5901x; 1.0533x over previous
#include <cuda_runtime.h>
#include <cuda_fp16.h>
#include <cstdint>

#define BB 2
#define DD 64
#define MAXN 50000
#define MAXE 800000
#define SCAN_B 1024
#define TRANS_BLOCKS 296

// ---------------- static device scratch (no allocations allowed) -----------
__device__ uint2 g_Ph[(size_t)MAXN * 32];      // fp16 P, [node][batch][64] = 256B/node
__device__ int   g_deg[MAXN];
__device__ int   g_off[MAXN + 1];              // block-local exclusive prefix
__device__ int   g_bsum[64];                   // per-scan-block base
__device__ uint2 g_rank[MAXE];                 // (rank_u, rank_v) per edge
__device__ uint2 g_adj[2 * MAXE];              // (nbr, gate-bits)

// ---------------- PDL intrinsics (sm_90+) -----------------------------------
__device__ __forceinline__ void gdc_wait() {
    asm volatile("griddepcontrol.wait;" ::: "memory");
}
__device__ __forceinline__ void gdc_launch_dependents() {
    asm volatile("griddepcontrol.launch_dependents;");
}

// ---------------- small helpers ---------------------------------------------
__device__ __forceinline__ unsigned long long pack2(float lo, float hi) {
    unsigned long long r;
    asm("mov.b64 %0, {%1, %2};" : "=l"(r) : "f"(lo), "f"(hi));
    return r;
}
__device__ __forceinline__ float2 unpack2(unsigned long long v) {
    float2 r;
    asm("mov.b64 {%0, %1}, %2;" : "=f"(r.x), "=f"(r.y) : "l"(v));
    return r;
}
__device__ __forceinline__ void ffma2(unsigned long long& d,
                                      unsigned long long a,
                                      unsigned long long b) {
    asm("fma.rn.f32x2 %0, %1, %2, %0;" : "+l"(d) : "l"(a), "l"(b));
}
__device__ __forceinline__ unsigned pack_h2(float a, float b) {
    __half2 h = __floats2half2_rn(a, b);
    return *reinterpret_cast<unsigned*>(&h);
}
__device__ __forceinline__ float2 unpack_h2(unsigned u) {
    __half2 h = *reinterpret_cast<__half2*>(&u);
    return __half22float2(h);
}

// ---------------------------------------------------------------------------
// Transform: P = prev @ W^T, persistent grid, PDL primary (fires at t~0).
// ---------------------------------------------------------------------------
__global__ __launch_bounds__(256)
void k_transform(const float* __restrict__ prev, const float* __restrict__ W,
                 int nRows, int N)
{
    gdc_launch_dependents();

    __shared__ float As[64][66];
    __shared__ float Wt[64][64];

    int tid = threadIdx.x;

#pragma unroll
    for (int j = 0; j < 4; j++) {
        int f4 = tid + j * 256;
        int e = f4 >> 4, k4 = f4 & 15;
        float4 w = reinterpret_cast<const float4*>(W)[f4];
        Wt[k4 * 4 + 0][e] = w.x;
        Wt[k4 * 4 + 1][e] = w.y;
        Wt[k4 * 4 + 2][e] = w.z;
        Wt[k4 * 4 + 3][e] = w.w;
    }

    int nTiles = (nRows + 63) >> 6;
    int colg = tid & 15;
    int rowg = tid >> 4;

    for (int tile = blockIdx.x; tile < nTiles; tile += gridDim.x) {
        int row0 = tile * 64;
        __syncthreads();

#pragma unroll
        for (int j = 0; j < 4; j++) {
            int f4 = tid + j * 256;
            int r = f4 >> 4, c4 = f4 & 15;
            float4 a = make_float4(0.f, 0.f, 0.f, 0.f);
            if (row0 + r < nRows)
                a = reinterpret_cast<const float4*>(prev)[(size_t)(row0 + r) * 16 + c4];
            As[c4 * 4 + 0][r] = a.x;
            As[c4 * 4 + 1][r] = a.y;
            As[c4 * 4 + 2][r] = a.z;
            As[c4 * 4 + 3][r] = a.w;
        }
        __syncthreads();

        unsigned long long acc[2][4] = {};

#pragma unroll 8
        for (int k = 0; k < 64; k++) {
            const unsigned long long* ar =
                reinterpret_cast<const unsigned long long*>(&As[k][rowg * 4]);
            unsigned long long A0 = ar[0];
            unsigned long long A1 = ar[1];
            float4 w = *reinterpret_cast<const float4*>(&Wt[k][colg * 4]);
            unsigned long long w0 = pack2(w.x, w.x);
            unsigned long long w1 = pack2(w.y, w.y);
            unsigned long long w2 = pack2(w.z, w.z);
            unsigned long long w3 = pack2(w.w, w.w);
            ffma2(acc[0][0], A0, w0); ffma2(acc[0][1], A0, w1);
            ffma2(acc[0][2], A0, w2); ffma2(acc[0][3], A0, w3);
            ffma2(acc[1][0], A1, w0); ffma2(acc[1][1], A1, w1);
            ffma2(acc[1][2], A1, w2); ffma2(acc[1][3], A1, w3);
        }

#pragma unroll
        for (int p = 0; p < 2; p++) {
            float2 v0 = unpack2(acc[p][0]);
            float2 v1 = unpack2(acc[p][1]);
            float2 v2 = unpack2(acc[p][2]);
            float2 v3 = unpack2(acc[p][3]);
            int rA = row0 + rowg * 4 + p * 2;
            int rB = rA + 1;
            if (rA < nRows) {
                int b = (rA >= N) ? 1 : 0;
                int n = rA - b * N;
                g_Ph[(size_t)n * 32 + b * 16 + colg] =
                    make_uint2(pack_h2(v0.x, v1.x), pack_h2(v2.x, v3.x));
            }
            if (rB < nRows) {
                int b = (rB >= N) ? 1 : 0;
                int n = rB - b * N;
                g_Ph[(size_t)n * 32 + b * 16 + colg] =
                    make_uint2(pack_h2(v0.y, v1.y), pack_h2(v2.y, v3.y));
            }
        }
    }
}

// ---------------------------------------------------------------------------
// Count + rank (PDL secondary, independent -> no wait).
// ---------------------------------------------------------------------------
__global__ __launch_bounds__(256)
void k_count_rank(const int* __restrict__ edges, int E)
{
    gdc_launch_dependents();
    int i = blockIdx.x * blockDim.x + threadIdx.x;
    int Eh = E >> 1;
    if (i < Eh) {
        int4 e2 = reinterpret_cast<const int4*>(edges)[i];
        unsigned r0 = atomicAdd(&g_deg[e2.x], 1);
        unsigned r1 = atomicAdd(&g_deg[e2.y], 1);
        unsigned r2 = atomicAdd(&g_deg[e2.z], 1);
        unsigned r3 = atomicAdd(&g_deg[e2.w], 1);
        reinterpret_cast<uint4*>(g_rank)[i] = make_uint4(r0, r1, r2, r3);
    } else if (i == Eh && (E & 1)) {
        int e = E - 1;
        int u = edges[2 * (size_t)e];
        int v = edges[2 * (size_t)e + 1];
        unsigned ru = atomicAdd(&g_deg[u], 1);
        unsigned rv = atomicAdd(&g_deg[v], 1);
        g_rank[e] = make_uint2(ru, rv);
    }
}

// ---------------------------------------------------------------------------
// 2-phase scan (PDL chain).
// ---------------------------------------------------------------------------
__global__ __launch_bounds__(SCAN_B)
void k_scan_local(int N)
{
    gdc_launch_dependents();
    gdc_wait();
    __shared__ int sh[SCAN_B];
    int t = threadIdx.x;
    int i = blockIdx.x * SCAN_B + t;
    int d = (i < N) ? g_deg[i] : 0;
    sh[t] = d;
    __syncthreads();
    for (int s = 1; s < SCAN_B; s <<= 1) {
        int o = (t >= s) ? sh[t - s] : 0;
        __syncthreads();
        sh[t] += o;
        __syncthreads();
    }
    if (i < N) g_off[i] = sh[t] - d;
    if (t == SCAN_B - 1) g_bsum[blockIdx.x] = sh[t];
}

__global__ __launch_bounds__(64)
void k_scan_bsum(int nBlocks)
{
    gdc_launch_dependents();
    gdc_wait();
    int t = threadIdx.x;
    int v = (t < nBlocks) ? g_bsum[t] : 0;
    __shared__ int sh[64];
    sh[t] = v;
    __syncthreads();
    for (int s = 1; s < 64; s <<= 1) {
        int o = (t >= s) ? sh[t - s] : 0;
        __syncthreads();
        sh[t] += o;
        __syncthreads();
    }
    if (t < nBlocks) g_bsum[t] = sh[t] - v;
}

// ---------------------------------------------------------------------------
// Atomic-free fill (PDL secondary of scan_bsum).
// ---------------------------------------------------------------------------
__global__ __launch_bounds__(256)
void k_fill(const int* __restrict__ edges, const float* __restrict__ status,
            int E)
{
    gdc_wait();
    int i = blockIdx.x * blockDim.x + threadIdx.x;
    int Eh = E >> 1;
    if (i < Eh) {
        int4  e2 = reinterpret_cast<const int4*>(edges)[i];
        uint4 r2 = reinterpret_cast<const uint4*>(g_rank)[i];
        float2 st = reinterpret_cast<const float2*>(status)[i];
        unsigned g0 = __float_as_uint(st.x);
        unsigned g1 = __float_as_uint(st.y);
        int o0 = g_off[e2.x] + g_bsum[e2.x >> 10] + (int)r2.x;
        int o1 = g_off[e2.y] + g_bsum[e2.y >> 10] + (int)r2.y;
        int o2 = g_off[e2.z] + g_bsum[e2.z >> 10] + (int)r2.z;
        int o3 = g_off[e2.w] + g_bsum[e2.w >> 10] + (int)r2.w;
        g_adj[o0] = make_uint2((unsigned)e2.y, g0);
        g_adj[o1] = make_uint2((unsigned)e2.x, g0);
        g_adj[o2] = make_uint2((unsigned)e2.w, g1);
        g_adj[o3] = make_uint2((unsigned)e2.z, g1);
    } else if (i == Eh && (E & 1)) {
        int e = E - 1;
        int u = edges[2 * (size_t)e];
        int v = edges[2 * (size_t)e + 1];
        uint2 r = g_rank[e];
        unsigned gb = __float_as_uint(status[e]);
        g_adj[g_off[u] + g_bsum[u >> 10] + (int)r.x] = make_uint2((unsigned)v, gb);
        g_adj[g_off[v] + g_bsum[v >> 10] + (int)r.y] = make_uint2((unsigned)u, gb);
    }
}

// ---------------------------------------------------------------------------
// Gather + epilogue (paired-edge LDG.128 layout).
// Warp = one node. half = lane>>4 selects edge of a pair; sl = lane&15 selects
// the 16B chunk of the 256B P record. 16 edges per main iteration = 8
// independent 16B load chains. Cross-half combine via shfl_xor(16); each lane
// writes exactly one float4 of the (node, both batches) output.
// ---------------------------------------------------------------------------
__global__ __launch_bounds__(128)
void k_gather_final(const float* __restrict__ nodef,
                    const float* __restrict__ edgef,
                    float* __restrict__ out, int N)
{
    int node = (blockIdx.x * blockDim.x + threadIdx.x) >> 5;
    if (node >= N) return;
    int lane = threadIdx.x & 31;
    int half = lane >> 4;
    int sl   = lane & 15;

    int beg = __ldg(&g_off[node]) + __ldg(&g_bsum[node >> 10]);
    int end = beg + __ldg(&g_deg[node]);

    const uint4* P4 = reinterpret_cast<const uint4*>(g_Ph);  // 16 uint4 / node

    float4 accA = make_float4(0.f, 0.f, 0.f, 0.f);   // halves 0-3 of chunk
    float4 accB = make_float4(0.f, 0.f, 0.f, 0.f);   // halves 4-7 of chunk

    int e = beg;
    for (; e + 15 < end; e += 16) {
        uint2 a0 = g_adj[e +  0 + half];
        uint2 a1 = g_adj[e +  2 + half];
        uint2 a2 = g_adj[e +  4 + half];
        uint2 a3 = g_adj[e +  6 + half];
        uint2 a4 = g_adj[e +  8 + half];
        uint2 a5 = g_adj[e + 10 + half];
        uint2 a6 = g_adj[e + 12 + half];
        uint2 a7 = g_adj[e + 14 + half];
        uint4 q0 = __ldg(P4 + (size_t)a0.x * 16 + sl);
        uint4 q1 = __ldg(P4 + (size_t)a1.x * 16 + sl);
        uint4 q2 = __ldg(P4 + (size_t)a2.x * 16 + sl);
        uint4 q3 = __ldg(P4 + (size_t)a3.x * 16 + sl);
        uint4 q4 = __ldg(P4 + (size_t)a4.x * 16 + sl);
        uint4 q5 = __ldg(P4 + (size_t)a5.x * 16 + sl);
        uint4 q6 = __ldg(P4 + (size_t)a6.x * 16 + sl);
        uint4 q7 = __ldg(P4 + (size_t)a7.x * 16 + sl);
#define ACC_Q(q, gbits)                                                   \
        {                                                                 \
            float g = __uint_as_float(gbits);                             \
            float2 f0 = unpack_h2((q).x), f1 = unpack_h2((q).y);          \
            float2 f2 = unpack_h2((q).z), f3 = unpack_h2((q).w);          \
            accA.x += f0.x * g; accA.y += f0.y * g;                       \
            accA.z += f1.x * g; accA.w += f1.y * g;                       \
            accB.x += f2.x * g; accB.y += f2.y * g;                       \
            accB.z += f3.x * g; accB.w += f3.y * g;                       \
        }
        ACC_Q(q0, a0.y) ACC_Q(q1, a1.y) ACC_Q(q2, a2.y) ACC_Q(q3, a3.y)
        ACC_Q(q4, a4.y) ACC_Q(q5, a5.y) ACC_Q(q6, a6.y) ACC_Q(q7, a7.y)
    }
    if (e < end) {
        // masked tail: up to 15 edges (8 predicated pairs)
#pragma unroll
        for (int p = 0; p < 8; p++) {
            int idx = e + p * 2 + half;
            int cl  = (idx < end) ? idx : beg;       // safe: beg < end here
            uint2 a = g_adj[cl];
            uint4 q = __ldg(P4 + (size_t)a.x * 16 + sl);
            unsigned gb = (idx < end) ? a.y : 0u;
            ACC_Q(q, gb)
        }
    }
#undef ACC_Q

    // combine even/odd edge halves
    accA.x += __shfl_xor_sync(0xffffffffu, accA.x, 16);
    accA.y += __shfl_xor_sync(0xffffffffu, accA.y, 16);
    accA.z += __shfl_xor_sync(0xffffffffu, accA.z, 16);
    accA.w += __shfl_xor_sync(0xffffffffu, accA.w, 16);
    accB.x += __shfl_xor_sync(0xffffffffu, accB.x, 16);
    accB.y += __shfl_xor_sync(0xffffffffu, accB.y, 16);
    accB.z += __shfl_xor_sync(0xffffffffu, accB.z, 16);
    accB.w += __shfl_xor_sync(0xffffffffu, accB.w, 16);

    // chunk sl covers halves [8*sl, 8*sl+8) of the 128-half record:
    // batch b = sl>>3, output float4s 2*(sl&7) + {0,1}; this lane writes #half.
    int b  = sl >> 3;
    int d8 = sl & 7;
    size_t o = ((size_t)b * N + node) * 16 + d8 * 2 + half;
    float4 nf = reinterpret_cast<const float4*>(nodef)[o];
    float4 ef = reinterpret_cast<const float4*>(edgef)[o];
    float4 r = (half == 0) ? accA : accB;

    float4 s;
    s.x = nf.x + ef.x + r.x;
    s.y = nf.y + ef.y + r.y;
    s.z = nf.z + ef.z + r.z;
    s.w = nf.w + ef.w + r.w;
    s.x = (s.x >= 0.f) ? s.x : 0.01f * s.x;
    s.y = (s.y >= 0.f) ? s.y : 0.01f * s.y;
    s.z = (s.z >= 0.f) ? s.z : 0.01f * s.z;
    s.w = (s.w >= 0.f) ? s.w : 0.01f * s.w;

    reinterpret_cast<float4*>(out)[o] = s;
}

// ---------------------------------------------------------------------------
template <typename K, typename... Args>
static inline void launch_pdl(K kernel, dim3 grid, dim3 block, Args... args)
{
    cudaLaunchConfig_t cfg = {};
    cfg.gridDim = grid;
    cfg.blockDim = block;
    cfg.dynamicSmemBytes = 0;
    cfg.stream = 0;
    cudaLaunchAttribute attr[1];
    attr[0].id = cudaLaunchAttributeProgrammaticStreamSerialization;
    attr[0].val.programmaticStreamSerializationAllowed = 1;
    cfg.attrs = attr;
    cfg.numAttrs = 1;
    cudaLaunchKernelEx(&cfg, kernel, args...);
}

extern "C" void kernel_launch(void* const* d_in, const int* in_sizes, int n_in,
                              void* d_out, int out_size)
{
    const float* prev  = (const float*)d_in[0];
    const int*   edges = (const int*)  d_in[1];
    const float* nodef = (const float*)d_in[2];
    const float* edgef = (const float*)d_in[3];
    const float* stat  = (const float*)d_in[4];
    const float* W     = (const float*)d_in[5];
    float* out = (float*)d_out;

    int E     = in_sizes[4];
    int nRows = in_sizes[0] / DD;   // B*N
    int N     = nRows / BB;

    int Epair  = (E >> 1) + 1;
    int nScanB = (N + SCAN_B - 1) / SCAN_B;

    void* degPtr = nullptr;
    cudaGetSymbolAddress(&degPtr, g_deg);
    cudaMemsetAsync(degPtr, 0, (size_t)N * sizeof(int));

    k_transform<<<TRANS_BLOCKS, 256>>>(prev, W, nRows, N);

    launch_pdl(k_count_rank, dim3((Epair + 255) / 256), dim3(256), edges, E);
    launch_pdl(k_scan_local, dim3(nScanB), dim3(SCAN_B), N);
    launch_pdl(k_scan_bsum,  dim3(1), dim3(64), nScanB);
    launch_pdl(k_fill,       dim3((Epair + 255) / 256), dim3(256), edges, stat, E);

    long long th = (long long)N * 32;
    k_gather_final<<<(unsigned)((th + 127) / 128), 128>>>(nodef, edgef, out, N);
}